// round 1
// baseline (speedup 1.0000x reference)
#include <cuda_runtime.h>
#include <math.h>

// ---------------------------------------------------------------------------
// Transformer block: B=8, T=1024, C=1024, H=16, D=64, TI=256, FF=4096, fp32.
// Pipeline:
//  1 LN(x)            -> bufa
//  2 bufa @ W_attn    -> big (qkv)
//  3 flash causal     -> bufb
//  4 bufb @ W_aproj+x -> x1
//  5 LN(x1)           -> bufa
//  6 bufa @ Wq        -> bufb
//  7 img  @ Wk        -> kbuf
//  8 img  @ Wv        -> vbuf
//  9 flash cross      -> bufc
// 10 bufc @ Wcproj+x1 -> x2
// 11 LN(x2)           -> bufa
// 12 bufa @ W_fc,gelu -> big
// 13 big @ W_mproj+x2 -> out
// ---------------------------------------------------------------------------

__device__ float g_big [33554432];  // 8192*4096 (qkv / fc activations)
__device__ float g_bufa[ 8388608];  // 8192*1024
__device__ float g_bufb[ 8388608];
__device__ float g_bufc[ 8388608];
__device__ float g_x1  [ 8388608];
__device__ float g_x2  [ 8388608];
__device__ float g_kbuf[ 2097152];  // 2048*1024
__device__ float g_vbuf[ 2097152];

// ------------------------------ LayerNorm ----------------------------------
// One block per row (C=1024), 256 threads, 4 floats per thread (two-pass).
__global__ __launch_bounds__(256) void ln_kernel(const float* __restrict__ x,
                                                 const float* __restrict__ gam,
                                                 const float* __restrict__ bet,
                                                 float* __restrict__ out) {
    __shared__ float sred[8];
    int row = blockIdx.x;
    int t = threadIdx.x;
    const float* xr = x + (size_t)row * 1024;
    float4 v = *(const float4*)(xr + t * 4);
    float s = v.x + v.y + v.z + v.w;
    #pragma unroll
    for (int o = 16; o > 0; o >>= 1) s += __shfl_xor_sync(0xffffffffu, s, o);
    if ((t & 31) == 0) sred[t >> 5] = s;
    __syncthreads();
    float mu = 0.f;
    #pragma unroll
    for (int i = 0; i < 8; i++) mu += sred[i];
    mu *= (1.0f / 1024.0f);
    __syncthreads();
    float dx = v.x - mu, dy = v.y - mu, dz = v.z - mu, dw = v.w - mu;
    float ss = dx * dx + dy * dy + dz * dz + dw * dw;
    #pragma unroll
    for (int o = 16; o > 0; o >>= 1) ss += __shfl_xor_sync(0xffffffffu, ss, o);
    if ((t & 31) == 0) sred[t >> 5] = ss;
    __syncthreads();
    float var = 0.f;
    #pragma unroll
    for (int i = 0; i < 8; i++) var += sred[i];
    var *= (1.0f / 1024.0f);
    float rstd = rsqrtf(var + 1e-5f);
    float4 gv = *(const float4*)(gam + t * 4);
    float4 bv = *(const float4*)(bet + t * 4);
    float4 o4;
    o4.x = dx * rstd * gv.x + bv.x;
    o4.y = dy * rstd * gv.y + bv.y;
    o4.z = dz * rstd * gv.z + bv.z;
    o4.w = dw * rstd * gv.w + bv.w;
    *(float4*)(out + (size_t)row * 1024 + t * 4) = o4;
}

// ------------------------------ SGEMM --------------------------------------
__device__ __forceinline__ float gelu_tanh(float x) {
    float x3 = x * x * x;
    return 0.5f * x * (1.0f + tanhf(0.7978845608f * (x + 0.044715f * x3)));
}

// C[M,N] = A[M,K] @ B[K,N] + bias (+res / gelu per MODE).
// 128x128 tile, BK=8, 256 threads, 8x8 per thread split 4+4 to avoid conflicts.
// All M,N multiples of 128; K multiple of 8. MODE: 0=bias, 1=bias+res, 2=bias+gelu.
template<int MODE>
__global__ __launch_bounds__(256, 2) void sgemm(const float* __restrict__ A,
                                                const float* __restrict__ B,
                                                const float* __restrict__ bias,
                                                const float* __restrict__ res,
                                                float* __restrict__ Cm,
                                                int M, int N, int K) {
    __shared__ float As[8][128];
    __shared__ float Bs[8][128];
    int tid = threadIdx.x;
    int tx = tid & 15, ty = tid >> 4;
    int row0 = blockIdx.y * 128;
    int col0 = blockIdx.x * 128;
    float acc[8][8];
    #pragma unroll
    for (int i = 0; i < 8; i++)
        #pragma unroll
        for (int j = 0; j < 8; j++) acc[i][j] = 0.f;

    int a_row = tid >> 1;
    int a_k4 = (tid & 1) * 4;
    int b_k = tid >> 5;
    int b_c4 = (tid & 31) * 4;
    const float* Ap = A + (size_t)(row0 + a_row) * K + a_k4;
    const float* Bp = B + (size_t)b_k * N + col0 + b_c4;

    for (int k0 = 0; k0 < K; k0 += 8) {
        float4 va = *(const float4*)(Ap + k0);
        float4 vb = *(const float4*)(Bp + (size_t)k0 * N);
        As[a_k4 + 0][a_row] = va.x;
        As[a_k4 + 1][a_row] = va.y;
        As[a_k4 + 2][a_row] = va.z;
        As[a_k4 + 3][a_row] = va.w;
        *(float4*)&Bs[b_k][b_c4] = vb;
        __syncthreads();
        #pragma unroll
        for (int kk = 0; kk < 8; kk++) {
            float4 a0 = *(const float4*)&As[kk][ty * 4];
            float4 a1 = *(const float4*)&As[kk][64 + ty * 4];
            float4 b0 = *(const float4*)&Bs[kk][tx * 4];
            float4 b1 = *(const float4*)&Bs[kk][64 + tx * 4];
            float ar[8] = {a0.x, a0.y, a0.z, a0.w, a1.x, a1.y, a1.z, a1.w};
            float br[8] = {b0.x, b0.y, b0.z, b0.w, b1.x, b1.y, b1.z, b1.w};
            #pragma unroll
            for (int i = 0; i < 8; i++)
                #pragma unroll
                for (int j = 0; j < 8; j++)
                    acc[i][j] += ar[i] * br[j];
        }
        __syncthreads();
    }

    #pragma unroll
    for (int i = 0; i < 8; i++) {
        int r = row0 + ((i < 4) ? (ty * 4 + i) : (64 + ty * 4 + i - 4));
        #pragma unroll
        for (int js = 0; js < 2; js++) {
            int c = col0 + js * 64 + tx * 4;
            float4 ov;
            float* po = &ov.x;
            #pragma unroll
            for (int j = 0; j < 4; j++) {
                float val = acc[i][js * 4 + j] + bias[c + j];
                if (MODE == 1) val += res[(size_t)r * N + c + j];
                if (MODE == 2) val = gelu_tanh(val);
                po[j] = val;
            }
            *(float4*)&Cm[(size_t)r * N + c] = ov;
        }
    }
}

// ------------------------------ Flash attention ----------------------------
// 64-query x 64-key tiles, D=64. 256 threads (16x16), 4x4 outputs/thread.
// Online softmax state (m,l) replicated across the 16 lanes owning a row via
// half-warp shuffle reductions. KsT smem reused as P after score compute.
template<bool CAUSAL>
__global__ __launch_bounds__(256) void flash_kernel(const float* __restrict__ Qb,
                                                    const float* __restrict__ Kb,
                                                    const float* __restrict__ Vb,
                                                    float* __restrict__ Ob,
                                                    int Tq, int Tk,
                                                    int qrs, int krs, int vrs, int ors,
                                                    float scale) {
    __shared__ float Qs[64][64];
    __shared__ float KP[64][64];   // K transposed [d][key], then P [row][key]
    __shared__ float Vs[64][64];   // [key][d]
    int tid = threadIdx.x;
    int tx = tid & 15, ty = tid >> 4;
    int bh = blockIdx.y;
    int b = bh >> 4, h = bh & 15;
    int q0 = blockIdx.x * 64;
    const float* Qbase = Qb + (size_t)b * Tq * qrs + h * 64;
    const float* Kbase = Kb + (size_t)b * Tk * krs + h * 64;
    const float* Vbase = Vb + (size_t)b * Tk * vrs + h * 64;

    #pragma unroll
    for (int it = 0; it < 4; it++) {
        int lin = tid + it * 256;
        int r = lin >> 4, d4 = (lin & 15) * 4;
        float4 v = *(const float4*)(Qbase + (size_t)(q0 + r) * qrs + d4);
        v.x *= scale; v.y *= scale; v.z *= scale; v.w *= scale;
        *(float4*)&Qs[r][d4] = v;
    }

    float o[4][4];
    #pragma unroll
    for (int i = 0; i < 4; i++)
        #pragma unroll
        for (int j = 0; j < 4; j++) o[i][j] = 0.f;
    float m_r[4] = {-1e30f, -1e30f, -1e30f, -1e30f};
    float l_r[4] = {0.f, 0.f, 0.f, 0.f};

    int ntiles = CAUSAL ? (blockIdx.x + 1) : (Tk >> 6);
    for (int kt = 0; kt < ntiles; kt++) {
        int k0 = kt * 64;
        __syncthreads();   // protect smem from previous iteration's readers
        #pragma unroll
        for (int it = 0; it < 4; it++) {
            int lin = tid + it * 256;
            int s = lin >> 4, d4 = (lin & 15) * 4;
            float4 kv = *(const float4*)(Kbase + (size_t)(k0 + s) * krs + d4);
            KP[d4 + 0][s] = kv.x;
            KP[d4 + 1][s] = kv.y;
            KP[d4 + 2][s] = kv.z;
            KP[d4 + 3][s] = kv.w;
            float4 vv = *(const float4*)(Vbase + (size_t)(k0 + s) * vrs + d4);
            *(float4*)&Vs[s][d4] = vv;
        }
        __syncthreads();

        // S = Q @ K^T  (rows ty*4+i, cols tx*4+j)
        float sc[4][4];
        #pragma unroll
        for (int i = 0; i < 4; i++)
            #pragma unroll
            for (int j = 0; j < 4; j++) sc[i][j] = 0.f;
        #pragma unroll 4
        for (int d4 = 0; d4 < 16; d4++) {
            float4 k0v = *(const float4*)&KP[d4 * 4 + 0][tx * 4];
            float4 k1v = *(const float4*)&KP[d4 * 4 + 1][tx * 4];
            float4 k2v = *(const float4*)&KP[d4 * 4 + 2][tx * 4];
            float4 k3v = *(const float4*)&KP[d4 * 4 + 3][tx * 4];
            #pragma unroll
            for (int i = 0; i < 4; i++) {
                float4 qv = *(const float4*)&Qs[ty * 4 + i][d4 * 4];
                sc[i][0] += qv.x * k0v.x + qv.y * k1v.x + qv.z * k2v.x + qv.w * k3v.x;
                sc[i][1] += qv.x * k0v.y + qv.y * k1v.y + qv.z * k2v.y + qv.w * k3v.y;
                sc[i][2] += qv.x * k0v.z + qv.y * k1v.z + qv.z * k2v.z + qv.w * k3v.z;
                sc[i][3] += qv.x * k0v.w + qv.y * k1v.w + qv.z * k2v.w + qv.w * k3v.w;
            }
        }
        if (CAUSAL && kt == blockIdx.x) {
            #pragma unroll
            for (int i = 0; i < 4; i++)
                #pragma unroll
                for (int j = 0; j < 4; j++)
                    if (k0 + tx * 4 + j > q0 + ty * 4 + i) sc[i][j] = -1e30f;
        }
        __syncthreads();   // everyone done reading KP(KsT) before writing P

        // Online softmax per row; lanes with same ty form a contiguous 16-lane
        // half-warp group -> xor-shuffle reduce stays within the group.
        #pragma unroll
        for (int i = 0; i < 4; i++) {
            float mx = fmaxf(fmaxf(sc[i][0], sc[i][1]), fmaxf(sc[i][2], sc[i][3]));
            #pragma unroll
            for (int off = 1; off < 16; off <<= 1)
                mx = fmaxf(mx, __shfl_xor_sync(0xffffffffu, mx, off));
            float mnew = fmaxf(m_r[i], mx);
            float p0 = __expf(sc[i][0] - mnew);
            float p1 = __expf(sc[i][1] - mnew);
            float p2 = __expf(sc[i][2] - mnew);
            float p3 = __expf(sc[i][3] - mnew);
            float ps = p0 + p1 + p2 + p3;
            #pragma unroll
            for (int off = 1; off < 16; off <<= 1)
                ps += __shfl_xor_sync(0xffffffffu, ps, off);
            float alpha = __expf(m_r[i] - mnew);
            l_r[i] = l_r[i] * alpha + ps;
            m_r[i] = mnew;
            o[i][0] *= alpha; o[i][1] *= alpha; o[i][2] *= alpha; o[i][3] *= alpha;
            *(float4*)&KP[ty * 4 + i][tx * 4] = make_float4(p0, p1, p2, p3);
        }
        __syncthreads();

        // O += P @ V  (cols are d-dims tx*4+j)
        #pragma unroll 4
        for (int k4 = 0; k4 < 16; k4++) {
            float4 v0 = *(const float4*)&Vs[k4 * 4 + 0][tx * 4];
            float4 v1 = *(const float4*)&Vs[k4 * 4 + 1][tx * 4];
            float4 v2 = *(const float4*)&Vs[k4 * 4 + 2][tx * 4];
            float4 v3 = *(const float4*)&Vs[k4 * 4 + 3][tx * 4];
            #pragma unroll
            for (int i = 0; i < 4; i++) {
                float4 pv = *(const float4*)&KP[ty * 4 + i][k4 * 4];
                o[i][0] += pv.x * v0.x + pv.y * v1.x + pv.z * v2.x + pv.w * v3.x;
                o[i][1] += pv.x * v0.y + pv.y * v1.y + pv.z * v2.y + pv.w * v3.y;
                o[i][2] += pv.x * v0.z + pv.y * v1.z + pv.z * v2.z + pv.w * v3.z;
                o[i][3] += pv.x * v0.w + pv.y * v1.w + pv.z * v2.w + pv.w * v3.w;
            }
        }
    }

    #pragma unroll
    for (int i = 0; i < 4; i++) {
        float inv = 1.0f / l_r[i];
        int r = q0 + ty * 4 + i;
        float4 ov = make_float4(o[i][0] * inv, o[i][1] * inv, o[i][2] * inv, o[i][3] * inv);
        *(float4*)(Ob + (size_t)(b * Tq + r) * ors + h * 64 + tx * 4) = ov;
    }
}

// ------------------------------ Launch -------------------------------------
extern "C" void kernel_launch(void* const* d_in, const int* in_sizes, int n_in,
                              void* d_out, int out_size) {
    (void)in_sizes; (void)n_in; (void)out_size;
    const float* x       = (const float*)d_in[0];
    const float* ximg    = (const float*)d_in[1];
    const float* ln1g    = (const float*)d_in[2];
    const float* ln1b    = (const float*)d_in[3];
    const float* ln2g    = (const float*)d_in[4];
    const float* ln2b    = (const float*)d_in[5];
    const float* W_attn  = (const float*)d_in[6];
    const float* b_attn  = (const float*)d_in[7];
    const float* W_aproj = (const float*)d_in[8];
    const float* b_aproj = (const float*)d_in[9];
    const float* Wq      = (const float*)d_in[10];
    const float* bq      = (const float*)d_in[11];
    const float* Wk      = (const float*)d_in[12];
    const float* bk      = (const float*)d_in[13];
    const float* Wv      = (const float*)d_in[14];
    const float* bv      = (const float*)d_in[15];
    const float* Wcproj  = (const float*)d_in[16];
    const float* bcproj  = (const float*)d_in[17];
    const float* W_fc    = (const float*)d_in[18];
    const float* b_fc    = (const float*)d_in[19];
    const float* W_mproj = (const float*)d_in[20];
    const float* b_mproj = (const float*)d_in[21];
    float* out = (float*)d_out;

    float *p_big, *p_a, *p_b, *p_c, *p_x1, *p_x2, *p_k, *p_v;
    cudaGetSymbolAddress((void**)&p_big, g_big);
    cudaGetSymbolAddress((void**)&p_a,   g_bufa);
    cudaGetSymbolAddress((void**)&p_b,   g_bufb);
    cudaGetSymbolAddress((void**)&p_c,   g_bufc);
    cudaGetSymbolAddress((void**)&p_x1,  g_x1);
    cudaGetSymbolAddress((void**)&p_x2,  g_x2);
    cudaGetSymbolAddress((void**)&p_k,   g_kbuf);
    cudaGetSymbolAddress((void**)&p_v,   g_vbuf);

    const float scale = 0.125f;  // 1/sqrt(64)

    // 1. h = LN(x)
    ln_kernel<<<8192, 256>>>(x, ln1g, ln1b, p_a);
    // 2. qkv = h @ W_attn + b_attn       [8192, 3072]
    sgemm<0><<<dim3(24, 64), 256>>>(p_a, W_attn, b_attn, nullptr, p_big, 8192, 3072, 1024);
    // 3. causal self-attention -> merged [8192, 1024]
    flash_kernel<true><<<dim3(16, 128), 256>>>(p_big, p_big + 1024, p_big + 2048, p_b,
                                               1024, 1024, 3072, 3072, 3072, 1024, scale);
    // 4. x1 = attnout @ W_aproj + b + x
    sgemm<1><<<dim3(8, 64), 256>>>(p_b, W_aproj, b_aproj, x, p_x1, 8192, 1024, 1024);
    // 5. ht = LN(x1)
    ln_kernel<<<8192, 256>>>(p_x1, ln1g, ln1b, p_a);
    // 6. q = ht @ Wq + bq
    sgemm<0><<<dim3(8, 64), 256>>>(p_a, Wq, bq, nullptr, p_b, 8192, 1024, 1024);
    // 7/8. k,v = img @ Wk/Wv             [2048, 1024]
    sgemm<0><<<dim3(8, 16), 256>>>(ximg, Wk, bk, nullptr, p_k, 2048, 1024, 1024);
    sgemm<0><<<dim3(8, 16), 256>>>(ximg, Wv, bv, nullptr, p_v, 2048, 1024, 1024);
    // 9. cross attention (no mask, 256 keys)
    flash_kernel<false><<<dim3(16, 128), 256>>>(p_b, p_k, p_v, p_c,
                                                1024, 256, 1024, 1024, 1024, 1024, scale);
    // 10. x2 = ca @ Wcproj + b + x1
    sgemm<1><<<dim3(8, 64), 256>>>(p_c, Wcproj, bcproj, p_x1, p_x2, 8192, 1024, 1024);
    // 11. h2 = LN(x2)
    ln_kernel<<<8192, 256>>>(p_x2, ln2g, ln2b, p_a);
    // 12. ff = gelu(h2 @ W_fc + b_fc)    [8192, 4096]
    sgemm<2><<<dim3(32, 64), 256>>>(p_a, W_fc, b_fc, nullptr, p_big, 8192, 4096, 1024);
    // 13. out = ff @ W_mproj + b + x2
    sgemm<1><<<dim3(8, 64), 256>>>(p_big, W_mproj, b_mproj, p_x2, out, 8192, 1024, 4096);
}

// round 4
// speedup vs baseline: 1.8449x; 1.8449x over previous
#include <cuda_runtime.h>
#include <cuda_bf16.h>
#include <math.h>
#include <stdint.h>

// ===========================================================================
// Transformer block, GB300 (built for base sm_103 target: tcgen05 PTX is
// rejected by this harness's ptxas, so tensor work goes through
// mma.sync.m16n8k16 bf16 HMMA). GEMMs use split-bf16 hi/lo with 3 products
// (AhBh + AhBl + AlBh) for ~2^-17 relative error. Flash attention fp32.
// ===========================================================================

__device__ __forceinline__ uint32_t smem_u32(const void* p) {
    uint32_t a;
    asm("{ .reg .u64 t; cvta.to.shared.u64 t, %1; cvt.u32.u64 %0, t; }" : "=r"(a) : "l"(p));
    return a;
}

#define CP16(dst, src) asm volatile("cp.async.cg.shared.global [%0], [%1], 16;" :: "r"(dst), "l"(src))
#define CP_COMMIT()    asm volatile("cp.async.commit_group;")
#define CP_WAIT1()     asm volatile("cp.async.wait_group 1;")
#define CP_WAIT0()     asm volatile("cp.async.wait_group 0;")

#define LDSM4(r0, r1, r2, r3, addr) \
    asm volatile("ldmatrix.sync.aligned.m8n8.x4.shared.b16 {%0,%1,%2,%3}, [%4];" \
        : "=r"(r0), "=r"(r1), "=r"(r2), "=r"(r3) : "r"(addr))

#define MMA_BF16(c, a, b0, b1) \
    asm volatile("mma.sync.aligned.m16n8k16.row.col.f32.bf16.bf16.f32 " \
        "{%0,%1,%2,%3}, {%4,%5,%6,%7}, {%8,%9}, {%0,%1,%2,%3};" \
        : "+f"((c)[0]), "+f"((c)[1]), "+f"((c)[2]), "+f"((c)[3]) \
        : "r"((a)[0]), "r"((a)[1]), "r"((a)[2]), "r"((a)[3]), "r"(b0), "r"(b1))

__device__ __forceinline__ void split_bf16(float v, __nv_bfloat16& h, __nv_bfloat16& l) {
    h = __float2bfloat16(v);
    l = __float2bfloat16(v - __bfloat162float(h));
}

__device__ __forceinline__ float gelu_tanh(float x) {
    float x3 = x * x * x;
    return 0.5f * x * (1.0f + tanhf(0.7978845608f * (x + 0.044715f * x3)));
}

// ------------------------------ device buffers -----------------------------
__device__ float g_big [25165824];  // 8192*3072 qkv fp32
__device__ float g_q   [ 8388608];
__device__ float g_kc  [ 2097152];
__device__ float g_vc  [ 2097152];
__device__ float g_x1  [ 8388608];
__device__ float g_x2  [ 8388608];
__device__ __nv_bfloat16 g_lnh[ 8388608], g_lnl[ 8388608];
__device__ __nv_bfloat16 g_ath[ 8388608], g_atl[ 8388608];
__device__ __nv_bfloat16 g_fch[33554432], g_fcl[33554432];
__device__ __nv_bfloat16 g_imh[ 2097152], g_iml[ 2097152];
// transposed+split weights: [N, K] bf16
__device__ __nv_bfloat16 w_attn_h[3145728], w_attn_l[3145728];
__device__ __nv_bfloat16 w_apr_h [1048576], w_apr_l [1048576];
__device__ __nv_bfloat16 w_q_h   [1048576], w_q_l   [1048576];
__device__ __nv_bfloat16 w_k_h   [1048576], w_k_l   [1048576];
__device__ __nv_bfloat16 w_v_h   [1048576], w_v_l   [1048576];
__device__ __nv_bfloat16 w_cpr_h [1048576], w_cpr_l [1048576];
__device__ __nv_bfloat16 w_fc_h  [4194304], w_fc_l  [4194304];
__device__ __nv_bfloat16 w_mpr_h [4194304], w_mpr_l [4194304];

// ------------------------- weight transpose + split ------------------------
__global__ __launch_bounds__(256) void wtrans(const float* __restrict__ W,
                                              __nv_bfloat16* __restrict__ Th,
                                              __nv_bfloat16* __restrict__ Tl,
                                              int K, int N) {
    __shared__ float t[32][33];
    int tx = threadIdx.x, ty = threadIdx.y;
    int n0 = blockIdx.x * 32, k0 = blockIdx.y * 32;
    #pragma unroll
    for (int i = 0; i < 32; i += 8)
        t[ty + i][tx] = W[(size_t)(k0 + ty + i) * N + n0 + tx];
    __syncthreads();
    #pragma unroll
    for (int i = 0; i < 32; i += 8) {
        float v = t[tx][ty + i];
        __nv_bfloat16 h, l;
        split_bf16(v, h, l);
        size_t o = (size_t)(n0 + ty + i) * K + k0 + tx;
        Th[o] = h; Tl[o] = l;
    }
}

__global__ __launch_bounds__(256) void fsplit(const float* __restrict__ x,
                                              __nv_bfloat16* __restrict__ oh,
                                              __nv_bfloat16* __restrict__ ol) {
    size_t i = ((size_t)blockIdx.x * 256 + threadIdx.x) * 4;
    float4 v = *(const float4*)(x + i);
    __nv_bfloat16 h0, l0, h1, l1, h2, l2, h3, l3;
    split_bf16(v.x, h0, l0); split_bf16(v.y, h1, l1);
    split_bf16(v.z, h2, l2); split_bf16(v.w, h3, l3);
    __nv_bfloat162 a, b;
    a.x = h0; a.y = h1; b.x = h2; b.y = h3;
    *(__nv_bfloat162*)(oh + i) = a; *(__nv_bfloat162*)(oh + i + 2) = b;
    a.x = l0; a.y = l1; b.x = l2; b.y = l3;
    *(__nv_bfloat162*)(ol + i) = a; *(__nv_bfloat162*)(ol + i + 2) = b;
}

// ------------------------------ LayerNorm ----------------------------------
__global__ __launch_bounds__(256) void ln_kernel(const float* __restrict__ x,
                                                 const float* __restrict__ gam,
                                                 const float* __restrict__ bet,
                                                 __nv_bfloat16* __restrict__ oh,
                                                 __nv_bfloat16* __restrict__ ol) {
    __shared__ float sred[8];
    int row = blockIdx.x;
    int t = threadIdx.x;
    const float* xr = x + (size_t)row * 1024;
    float4 v = *(const float4*)(xr + t * 4);
    float s = v.x + v.y + v.z + v.w;
    #pragma unroll
    for (int o = 16; o > 0; o >>= 1) s += __shfl_xor_sync(0xffffffffu, s, o);
    if ((t & 31) == 0) sred[t >> 5] = s;
    __syncthreads();
    float mu = 0.f;
    #pragma unroll
    for (int i = 0; i < 8; i++) mu += sred[i];
    mu *= (1.0f / 1024.0f);
    __syncthreads();
    float dx = v.x - mu, dy = v.y - mu, dz = v.z - mu, dw = v.w - mu;
    float ss = dx * dx + dy * dy + dz * dz + dw * dw;
    #pragma unroll
    for (int o = 16; o > 0; o >>= 1) ss += __shfl_xor_sync(0xffffffffu, ss, o);
    if ((t & 31) == 0) sred[t >> 5] = ss;
    __syncthreads();
    float var = 0.f;
    #pragma unroll
    for (int i = 0; i < 8; i++) var += sred[i];
    var *= (1.0f / 1024.0f);
    float rstd = rsqrtf(var + 1e-5f);
    float4 gv = *(const float4*)(gam + t * 4);
    float4 bv = *(const float4*)(bet + t * 4);
    float r0 = dx * rstd * gv.x + bv.x;
    float r1 = dy * rstd * gv.y + bv.y;
    float r2 = dz * rstd * gv.z + bv.z;
    float r3 = dw * rstd * gv.w + bv.w;
    size_t o = (size_t)row * 1024 + t * 4;
    __nv_bfloat16 h0, l0, h1, l1, h2, l2, h3, l3;
    split_bf16(r0, h0, l0); split_bf16(r1, h1, l1);
    split_bf16(r2, h2, l2); split_bf16(r3, h3, l3);
    __nv_bfloat162 a, b;
    a.x = h0; a.y = h1; b.x = h2; b.y = h3;
    *(__nv_bfloat162*)(oh + o) = a; *(__nv_bfloat162*)(oh + o + 2) = b;
    a.x = l0; a.y = l1; b.x = l2; b.y = l3;
    *(__nv_bfloat162*)(ol + o) = a; *(__nv_bfloat162*)(ol + o + 2) = b;
}

// ---------------------------- HMMA GEMM ------------------------------------
// D[M,N] = A @ W^T variant: A as bf16 hi/lo [M,K]; W transposed [N,K] hi/lo.
// CTA tile 128x128, BK=32, 512 threads = 16 warps in 4x4, warp tile 32x32.
// Double-buffered smem via cp.async. Smem rows padded to 40 halves (80B) ->
// ldmatrix conflict-free (80/4=20 banks stride covers all 32 banks over 8 rows).
// MODE 0: fp32 out+bias; 1: +res; 2: gelu -> bf16 hi/lo out.
template<int MODE>
__global__ __launch_bounds__(512) void hmma_gemm(
    const __nv_bfloat16* __restrict__ Ah, const __nv_bfloat16* __restrict__ Al,
    const __nv_bfloat16* __restrict__ Bh, const __nv_bfloat16* __restrict__ Bl,
    const float* __restrict__ bias, const float* __restrict__ res,
    float* __restrict__ outf,
    __nv_bfloat16* __restrict__ outh, __nv_bfloat16* __restrict__ outl,
    int M, int N, int K) {
    extern __shared__ __align__(128) uint8_t smem[];
    const uint32_t STG = 40960;                 // bytes per stage
    const uint32_t OA_H = 0, OA_L = 10240, OB_H = 20480, OB_L = 30720;
    uint32_t sb = smem_u32(smem);
    int tid = threadIdx.x, wid = tid >> 5, lane = tid & 31;
    int row0 = blockIdx.y * 128, col0 = blockIdx.x * 128;
    int wm = wid >> 2, wn = wid & 3;

    // loader mapping: 512 threads, each copies one 16B seg per matrix per chunk
    int lrow = tid >> 2, lseg = tid & 3;
    size_t ga = (size_t)(row0 + lrow) * K + lseg * 8;
    size_t gb = (size_t)(col0 + lrow) * K + lseg * 8;
    uint32_t so = lrow * 80 + lseg * 16;

    float c[2][4][4];
    #pragma unroll
    for (int i = 0; i < 2; i++)
        #pragma unroll
        for (int j = 0; j < 4; j++)
            #pragma unroll
            for (int q = 0; q < 4; q++) c[i][j][q] = 0.f;

    const int nk = K >> 5;
    {   // prologue: stage 0
        uint32_t d = sb + so;
        CP16(d + OA_H, Ah + ga); CP16(d + OA_L, Al + ga);
        CP16(d + OB_H, Bh + gb); CP16(d + OB_L, Bl + gb);
        CP_COMMIT();
    }
    for (int ch = 0; ch < nk; ch++) {
        if (ch + 1 < nk) {
            uint32_t d = sb + ((ch + 1) & 1) * STG + so;
            int ko = (ch + 1) << 5;
            CP16(d + OA_H, Ah + ga + ko); CP16(d + OA_L, Al + ga + ko);
            CP16(d + OB_H, Bh + gb + ko); CP16(d + OB_L, Bl + gb + ko);
            CP_COMMIT();
            CP_WAIT1();
        } else {
            CP_WAIT0();
        }
        __syncthreads();
        uint32_t base = sb + (ch & 1) * STG;

        #pragma unroll
        for (int s = 0; s < 2; s++) {           // two k16 steps per 32-chunk
            uint32_t ah[2][4], al[2][4], bh[2][4], bl[2][4];
            // A fragments: lanes 0-15 rows @k0, lanes 16-31 rows @k0+16B
            #pragma unroll
            for (int mb = 0; mb < 2; mb++) {
                uint32_t ra = base + OA_H +
                    (uint32_t)(wm * 32 + mb * 16 + (lane & 15)) * 80 + s * 32 + (lane >> 4) * 16;
                LDSM4(ah[mb][0], ah[mb][1], ah[mb][2], ah[mb][3], ra);
                uint32_t rl = ra + (OA_L - OA_H);
                LDSM4(al[mb][0], al[mb][1], al[mb][2], al[mb][3], rl);
            }
            // B fragments: grp0: n-blk0@k0, grp1: n-blk0@k8, grp2: n-blk1@k0, grp3: n-blk1@k8
            {
                int grp = lane >> 3, idx = lane & 7;
                #pragma unroll
                for (int nb = 0; nb < 2; nb++) {
                    uint32_t rb = base + OB_H +
                        (uint32_t)(wn * 32 + nb * 16 + ((grp >> 1) << 3) + idx) * 80 +
                        s * 32 + (grp & 1) * 16;
                    LDSM4(bh[nb][0], bh[nb][1], bh[nb][2], bh[nb][3], rb);
                    uint32_t rbl = rb + (OB_L - OB_H);
                    LDSM4(bl[nb][0], bl[nb][1], bl[nb][2], bl[nb][3], rbl);
                }
            }
            #pragma unroll
            for (int mb = 0; mb < 2; mb++) {
                #pragma unroll
                for (int j = 0; j < 4; j++) {
                    int nb = j >> 1, k2 = (j & 1) * 2;
                    uint32_t b0h = bh[nb][k2], b1h = bh[nb][k2 + 1];
                    uint32_t b0l = bl[nb][k2], b1l = bl[nb][k2 + 1];
                    MMA_BF16(c[mb][j], ah[mb], b0h, b1h);
                    MMA_BF16(c[mb][j], ah[mb], b0l, b1l);
                    MMA_BF16(c[mb][j], al[mb], b0h, b1h);
                }
            }
        }
        __syncthreads();
    }

    // epilogue: C frag (m16n8): c0,c1 row g=lane>>2 cols 2t,2t+1; c2,c3 row g+8
    #pragma unroll
    for (int mb = 0; mb < 2; mb++) {
        #pragma unroll
        for (int j = 0; j < 4; j++) {
            int col = col0 + wn * 32 + j * 8 + 2 * (lane & 3);
            float2 bv = *(const float2*)(bias + col);
            #pragma unroll
            for (int half = 0; half < 2; half++) {
                int r = row0 + wm * 32 + mb * 16 + (lane >> 2) + half * 8;
                float v0 = c[mb][j][half * 2 + 0] + bv.x;
                float v1 = c[mb][j][half * 2 + 1] + bv.y;
                if (MODE == 1) {
                    float2 rv = *(const float2*)(res + (size_t)r * N + col);
                    v0 += rv.x; v1 += rv.y;
                }
                if (MODE == 2) {
                    v0 = gelu_tanh(v0); v1 = gelu_tanh(v1);
                    __nv_bfloat16 h0, l0, h1, l1;
                    split_bf16(v0, h0, l0); split_bf16(v1, h1, l1);
                    size_t o = (size_t)r * N + col;
                    __nv_bfloat162 a;
                    a.x = h0; a.y = h1; *(__nv_bfloat162*)(outh + o) = a;
                    a.x = l0; a.y = l1; *(__nv_bfloat162*)(outl + o) = a;
                } else {
                    *(float2*)(outf + (size_t)r * N + col) = make_float2(v0, v1);
                }
            }
        }
    }
}

// ------------------------------ Flash attention ----------------------------
template<bool CAUSAL>
__global__ __launch_bounds__(256) void flash_kernel(const float* __restrict__ Qb,
                                                    const float* __restrict__ Kb,
                                                    const float* __restrict__ Vb,
                                                    __nv_bfloat16* __restrict__ Oh,
                                                    __nv_bfloat16* __restrict__ Ol,
                                                    int Tq, int Tk,
                                                    int qrs, int krs, int vrs,
                                                    float scale) {
    __shared__ float Qs[64][64];
    __shared__ float KP[64][64];
    __shared__ float Vs[64][64];
    int tid = threadIdx.x;
    int tx = tid & 15, ty = tid >> 4;
    int bh = blockIdx.y;
    int b = bh >> 4, h = bh & 15;
    int q0 = blockIdx.x * 64;
    const float* Qbase = Qb + (size_t)b * Tq * qrs + h * 64;
    const float* Kbase = Kb + (size_t)b * Tk * krs + h * 64;
    const float* Vbase = Vb + (size_t)b * Tk * vrs + h * 64;

    #pragma unroll
    for (int it = 0; it < 4; it++) {
        int lin = tid + it * 256;
        int r = lin >> 4, d4 = (lin & 15) * 4;
        float4 v = *(const float4*)(Qbase + (size_t)(q0 + r) * qrs + d4);
        v.x *= scale; v.y *= scale; v.z *= scale; v.w *= scale;
        *(float4*)&Qs[r][d4] = v;
    }

    float o[4][4];
    #pragma unroll
    for (int i = 0; i < 4; i++)
        #pragma unroll
        for (int j = 0; j < 4; j++) o[i][j] = 0.f;
    float m_r[4] = {-1e30f, -1e30f, -1e30f, -1e30f};
    float l_r[4] = {0.f, 0.f, 0.f, 0.f};

    int ntiles = CAUSAL ? (blockIdx.x + 1) : (Tk >> 6);
    for (int kt = 0; kt < ntiles; kt++) {
        int k0 = kt * 64;
        __syncthreads();
        #pragma unroll
        for (int it = 0; it < 4; it++) {
            int lin = tid + it * 256;
            int s = lin >> 4, d4 = (lin & 15) * 4;
            float4 kv = *(const float4*)(Kbase + (size_t)(k0 + s) * krs + d4);
            KP[d4 + 0][s] = kv.x;
            KP[d4 + 1][s] = kv.y;
            KP[d4 + 2][s] = kv.z;
            KP[d4 + 3][s] = kv.w;
            float4 vv = *(const float4*)(Vbase + (size_t)(k0 + s) * vrs + d4);
            *(float4*)&Vs[s][d4] = vv;
        }
        __syncthreads();

        float sc[4][4];
        #pragma unroll
        for (int i = 0; i < 4; i++)
            #pragma unroll
            for (int j = 0; j < 4; j++) sc[i][j] = 0.f;
        #pragma unroll 4
        for (int d4 = 0; d4 < 16; d4++) {
            float4 k0v = *(const float4*)&KP[d4 * 4 + 0][tx * 4];
            float4 k1v = *(const float4*)&KP[d4 * 4 + 1][tx * 4];
            float4 k2v = *(const float4*)&KP[d4 * 4 + 2][tx * 4];
            float4 k3v = *(const float4*)&KP[d4 * 4 + 3][tx * 4];
            #pragma unroll
            for (int i = 0; i < 4; i++) {
                float4 qv = *(const float4*)&Qs[ty * 4 + i][d4 * 4];
                sc[i][0] += qv.x * k0v.x + qv.y * k1v.x + qv.z * k2v.x + qv.w * k3v.x;
                sc[i][1] += qv.x * k0v.y + qv.y * k1v.y + qv.z * k2v.y + qv.w * k3v.y;
                sc[i][2] += qv.x * k0v.z + qv.y * k1v.z + qv.z * k2v.z + qv.w * k3v.z;
                sc[i][3] += qv.x * k0v.w + qv.y * k1v.w + qv.z * k2v.w + qv.w * k3v.w;
            }
        }
        if (CAUSAL && kt == blockIdx.x) {
            #pragma unroll
            for (int i = 0; i < 4; i++)
                #pragma unroll
                for (int j = 0; j < 4; j++)
                    if (k0 + tx * 4 + j > q0 + ty * 4 + i) sc[i][j] = -1e30f;
        }
        __syncthreads();

        #pragma unroll
        for (int i = 0; i < 4; i++) {
            float mx = fmaxf(fmaxf(sc[i][0], sc[i][1]), fmaxf(sc[i][2], sc[i][3]));
            #pragma unroll
            for (int off = 1; off < 16; off <<= 1)
                mx = fmaxf(mx, __shfl_xor_sync(0xffffffffu, mx, off));
            float mnew = fmaxf(m_r[i], mx);
            float p0 = __expf(sc[i][0] - mnew);
            float p1 = __expf(sc[i][1] - mnew);
            float p2 = __expf(sc[i][2] - mnew);
            float p3 = __expf(sc[i][3] - mnew);
            float ps = p0 + p1 + p2 + p3;
            #pragma unroll
            for (int off = 1; off < 16; off <<= 1)
                ps += __shfl_xor_sync(0xffffffffu, ps, off);
            float alpha = __expf(m_r[i] - mnew);
            l_r[i] = l_r[i] * alpha + ps;
            m_r[i] = mnew;
            o[i][0] *= alpha; o[i][1] *= alpha; o[i][2] *= alpha; o[i][3] *= alpha;
            *(float4*)&KP[ty * 4 + i][tx * 4] = make_float4(p0, p1, p2, p3);
        }
        __syncthreads();

        #pragma unroll 4
        for (int k4 = 0; k4 < 16; k4++) {
            float4 v0 = *(const float4*)&Vs[k4 * 4 + 0][tx * 4];
            float4 v1 = *(const float4*)&Vs[k4 * 4 + 1][tx * 4];
            float4 v2 = *(const float4*)&Vs[k4 * 4 + 2][tx * 4];
            float4 v3 = *(const float4*)&Vs[k4 * 4 + 3][tx * 4];
            #pragma unroll
            for (int i = 0; i < 4; i++) {
                float4 pv = *(const float4*)&KP[ty * 4 + i][k4 * 4];
                o[i][0] += pv.x * v0.x + pv.y * v1.x + pv.z * v2.x + pv.w * v3.x;
                o[i][1] += pv.x * v0.y + pv.y * v1.y + pv.z * v2.y + pv.w * v3.y;
                o[i][2] += pv.x * v0.z + pv.y * v1.z + pv.z * v2.z + pv.w * v3.z;
                o[i][3] += pv.x * v0.w + pv.y * v1.w + pv.z * v2.w + pv.w * v3.w;
            }
        }
    }

    #pragma unroll
    for (int i = 0; i < 4; i++) {
        float inv = 1.0f / l_r[i];
        int orow = b * Tq + q0 + ty * 4 + i;
        size_t obase = (size_t)orow * 1024 + h * 64 + tx * 4;
        float v0 = o[i][0] * inv, v1 = o[i][1] * inv, v2 = o[i][2] * inv, v3 = o[i][3] * inv;
        __nv_bfloat16 h0, l0, h1, l1, h2, l2, h3, l3;
        split_bf16(v0, h0, l0); split_bf16(v1, h1, l1);
        split_bf16(v2, h2, l2); split_bf16(v3, h3, l3);
        __nv_bfloat162 a, bb;
        a.x = h0; a.y = h1; bb.x = h2; bb.y = h3;
        *(__nv_bfloat162*)(Oh + obase) = a; *(__nv_bfloat162*)(Oh + obase + 2) = bb;
        a.x = l0; a.y = l1; bb.x = l2; bb.y = l3;
        *(__nv_bfloat162*)(Ol + obase) = a; *(__nv_bfloat162*)(Ol + obase + 2) = bb;
    }
}

// ------------------------------ Launch -------------------------------------
extern "C" void kernel_launch(void* const* d_in, const int* in_sizes, int n_in,
                              void* d_out, int out_size) {
    (void)in_sizes; (void)n_in; (void)out_size;
    const float* x       = (const float*)d_in[0];
    const float* ximg    = (const float*)d_in[1];
    const float* ln1g    = (const float*)d_in[2];
    const float* ln1b    = (const float*)d_in[3];
    const float* ln2g    = (const float*)d_in[4];
    const float* ln2b    = (const float*)d_in[5];
    const float* W_attn  = (const float*)d_in[6];
    const float* b_attn  = (const float*)d_in[7];
    const float* W_aproj = (const float*)d_in[8];
    const float* b_aproj = (const float*)d_in[9];
    const float* Wq      = (const float*)d_in[10];
    const float* bq      = (const float*)d_in[11];
    const float* Wk      = (const float*)d_in[12];
    const float* bk      = (const float*)d_in[13];
    const float* Wv      = (const float*)d_in[14];
    const float* bv      = (const float*)d_in[15];
    const float* Wcproj  = (const float*)d_in[16];
    const float* bcproj  = (const float*)d_in[17];
    const float* W_fc    = (const float*)d_in[18];
    const float* b_fc    = (const float*)d_in[19];
    const float* W_mproj = (const float*)d_in[20];
    const float* b_mproj = (const float*)d_in[21];
    float* out = (float*)d_out;

    float *p_big, *p_q, *p_kc, *p_vc, *p_x1, *p_x2;
    __nv_bfloat16 *p_lnh, *p_lnl, *p_ath, *p_atl, *p_fch, *p_fcl, *p_imh, *p_iml;
    __nv_bfloat16 *pw_attn_h, *pw_attn_l, *pw_apr_h, *pw_apr_l, *pw_q_h, *pw_q_l;
    __nv_bfloat16 *pw_k_h, *pw_k_l, *pw_v_h, *pw_v_l, *pw_cpr_h, *pw_cpr_l;
    __nv_bfloat16 *pw_fc_h, *pw_fc_l, *pw_mpr_h, *pw_mpr_l;
    cudaGetSymbolAddress((void**)&p_big, g_big);
    cudaGetSymbolAddress((void**)&p_q,   g_q);
    cudaGetSymbolAddress((void**)&p_kc,  g_kc);
    cudaGetSymbolAddress((void**)&p_vc,  g_vc);
    cudaGetSymbolAddress((void**)&p_x1,  g_x1);
    cudaGetSymbolAddress((void**)&p_x2,  g_x2);
    cudaGetSymbolAddress((void**)&p_lnh, g_lnh);
    cudaGetSymbolAddress((void**)&p_lnl, g_lnl);
    cudaGetSymbolAddress((void**)&p_ath, g_ath);
    cudaGetSymbolAddress((void**)&p_atl, g_atl);
    cudaGetSymbolAddress((void**)&p_fch, g_fch);
    cudaGetSymbolAddress((void**)&p_fcl, g_fcl);
    cudaGetSymbolAddress((void**)&p_imh, g_imh);
    cudaGetSymbolAddress((void**)&p_iml, g_iml);
    cudaGetSymbolAddress((void**)&pw_attn_h, w_attn_h);
    cudaGetSymbolAddress((void**)&pw_attn_l, w_attn_l);
    cudaGetSymbolAddress((void**)&pw_apr_h, w_apr_h);
    cudaGetSymbolAddress((void**)&pw_apr_l, w_apr_l);
    cudaGetSymbolAddress((void**)&pw_q_h, w_q_h);
    cudaGetSymbolAddress((void**)&pw_q_l, w_q_l);
    cudaGetSymbolAddress((void**)&pw_k_h, w_k_h);
    cudaGetSymbolAddress((void**)&pw_k_l, w_k_l);
    cudaGetSymbolAddress((void**)&pw_v_h, w_v_h);
    cudaGetSymbolAddress((void**)&pw_v_l, w_v_l);
    cudaGetSymbolAddress((void**)&pw_cpr_h, w_cpr_h);
    cudaGetSymbolAddress((void**)&pw_cpr_l, w_cpr_l);
    cudaGetSymbolAddress((void**)&pw_fc_h, w_fc_h);
    cudaGetSymbolAddress((void**)&pw_fc_l, w_fc_l);
    cudaGetSymbolAddress((void**)&pw_mpr_h, w_mpr_h);
    cudaGetSymbolAddress((void**)&pw_mpr_l, w_mpr_l);

    const int SMEM_GEMM = 81920;
    cudaFuncSetAttribute(hmma_gemm<0>, cudaFuncAttributeMaxDynamicSharedMemorySize, SMEM_GEMM);
    cudaFuncSetAttribute(hmma_gemm<1>, cudaFuncAttributeMaxDynamicSharedMemorySize, SMEM_GEMM);
    cudaFuncSetAttribute(hmma_gemm<2>, cudaFuncAttributeMaxDynamicSharedMemorySize, SMEM_GEMM);

    const float scale = 0.125f;  // 1/sqrt(64)
    dim3 tb(32, 8);

    // weight prep: transpose + bf16 split
    wtrans<<<dim3(96, 32), tb>>>(W_attn, pw_attn_h, pw_attn_l, 1024, 3072);
    wtrans<<<dim3(32, 32), tb>>>(W_aproj, pw_apr_h, pw_apr_l, 1024, 1024);
    wtrans<<<dim3(32, 32), tb>>>(Wq, pw_q_h, pw_q_l, 1024, 1024);
    wtrans<<<dim3(32, 32), tb>>>(Wk, pw_k_h, pw_k_l, 1024, 1024);
    wtrans<<<dim3(32, 32), tb>>>(Wv, pw_v_h, pw_v_l, 1024, 1024);
    wtrans<<<dim3(32, 32), tb>>>(Wcproj, pw_cpr_h, pw_cpr_l, 1024, 1024);
    wtrans<<<dim3(128, 32), tb>>>(W_fc, pw_fc_h, pw_fc_l, 1024, 4096);
    wtrans<<<dim3(32, 128), tb>>>(W_mproj, pw_mpr_h, pw_mpr_l, 4096, 1024);
    fsplit<<<2048, 256>>>(ximg, p_imh, p_iml);

    // 1. LN(x) -> bf16 hi/lo
    ln_kernel<<<8192, 256>>>(x, ln1g, ln1b, p_lnh, p_lnl);
    // 2. qkv = LN(x) @ W_attn + b  (fp32 out for flash)
    hmma_gemm<0><<<dim3(24, 64), 512, SMEM_GEMM>>>(p_lnh, p_lnl, pw_attn_h, pw_attn_l,
                                                   b_attn, nullptr, p_big, nullptr, nullptr,
                                                   8192, 3072, 1024);
    // 3. causal self-attention -> bf16 hi/lo
    flash_kernel<true><<<dim3(16, 128), 256>>>(p_big, p_big + 1024, p_big + 2048,
                                               p_ath, p_atl, 1024, 1024,
                                               3072, 3072, 3072, scale);
    // 4. x1 = sa @ W_aproj + b + x
    hmma_gemm<1><<<dim3(8, 64), 512, SMEM_GEMM>>>(p_ath, p_atl, pw_apr_h, pw_apr_l,
                                                  b_aproj, x, p_x1, nullptr, nullptr,
                                                  8192, 1024, 1024);
    // 5. LN(x1)
    ln_kernel<<<8192, 256>>>(p_x1, ln1g, ln1b, p_lnh, p_lnl);
    // 6. q = LN(x1) @ Wq + bq (fp32)
    hmma_gemm<0><<<dim3(8, 64), 512, SMEM_GEMM>>>(p_lnh, p_lnl, pw_q_h, pw_q_l,
                                                  bq, nullptr, p_q, nullptr, nullptr,
                                                  8192, 1024, 1024);
    // 7/8. k,v = img @ Wk/Wv (fp32)
    hmma_gemm<0><<<dim3(8, 16), 512, SMEM_GEMM>>>(p_imh, p_iml, pw_k_h, pw_k_l,
                                                  bk, nullptr, p_kc, nullptr, nullptr,
                                                  2048, 1024, 1024);
    hmma_gemm<0><<<dim3(8, 16), 512, SMEM_GEMM>>>(p_imh, p_iml, pw_v_h, pw_v_l,
                                                  bv, nullptr, p_vc, nullptr, nullptr,
                                                  2048, 1024, 1024);
    // 9. cross attention -> bf16 hi/lo
    flash_kernel<false><<<dim3(16, 128), 256>>>(p_q, p_kc, p_vc, p_ath, p_atl,
                                                1024, 256, 1024, 1024, 1024, scale);
    // 10. x2 = ca @ Wcproj + b + x1
    hmma_gemm<1><<<dim3(8, 64), 512, SMEM_GEMM>>>(p_ath, p_atl, pw_cpr_h, pw_cpr_l,
                                                  bcproj, p_x1, p_x2, nullptr, nullptr,
                                                  8192, 1024, 1024);
    // 11. LN(x2)
    ln_kernel<<<8192, 256>>>(p_x2, ln2g, ln2b, p_lnh, p_lnl);
    // 12. ff = gelu(LN(x2) @ W_fc + b) -> bf16 hi/lo
    hmma_gemm<2><<<dim3(32, 64), 512, SMEM_GEMM>>>(p_lnh, p_lnl, pw_fc_h, pw_fc_l,
                                                   b_fc, nullptr, nullptr, p_fch, p_fcl,
                                                   8192, 4096, 1024);
    // 13. out = ff @ W_mproj + b + x2
    hmma_gemm<1><<<dim3(8, 64), 512, SMEM_GEMM>>>(p_fch, p_fcl, pw_mpr_h, pw_mpr_l,
                                                  b_mproj, p_x2, out, nullptr, nullptr,
                                                  8192, 1024, 4096);
}

// round 10
// speedup vs baseline: 2.2046x; 1.1950x over previous
#include <cuda_runtime.h>
#include <cuda_bf16.h>
#include <math.h>
#include <stdint.h>

// ===========================================================================
// Transformer block, GB300, base sm_103 target (no tcgen05 in this harness).
// GEMMs + flash attention both on mma.sync.m16n8k16 bf16 with split-bf16
// hi/lo 3-product precision recovery (~2^-17 rel error).
// ===========================================================================

__device__ __forceinline__ uint32_t smem_u32(const void* p) {
    uint32_t a;
    asm("{ .reg .u64 t; cvta.to.shared.u64 t, %1; cvt.u32.u64 %0, t; }" : "=r"(a) : "l"(p));
    return a;
}

#define CP16(dst, src) asm volatile("cp.async.cg.shared.global [%0], [%1], 16;" :: "r"(dst), "l"(src))
#define CP_COMMIT()    asm volatile("cp.async.commit_group;")
#define CP_WAIT1()     asm volatile("cp.async.wait_group 1;")
#define CP_WAIT0()     asm volatile("cp.async.wait_group 0;")

#define LDSM4(r0, r1, r2, r3, addr) \
    asm volatile("ldmatrix.sync.aligned.m8n8.x4.shared.b16 {%0,%1,%2,%3}, [%4];" \
        : "=r"(r0), "=r"(r1), "=r"(r2), "=r"(r3) : "r"(addr))

#define MMA_BF16(c, a, b0, b1) \
    asm volatile("mma.sync.aligned.m16n8k16.row.col.f32.bf16.bf16.f32 " \
        "{%0,%1,%2,%3}, {%4,%5,%6,%7}, {%8,%9}, {%0,%1,%2,%3};" \
        : "+f"((c)[0]), "+f"((c)[1]), "+f"((c)[2]), "+f"((c)[3]) \
        : "r"((a)[0]), "r"((a)[1]), "r"((a)[2]), "r"((a)[3]), "r"(b0), "r"(b1))

__device__ __forceinline__ void split_bf16(float v, __nv_bfloat16& h, __nv_bfloat16& l) {
    h = __float2bfloat16(v);
    l = __float2bfloat16(v - __bfloat162float(h));
}
__device__ __forceinline__ uint32_t pack_hi(float a, float b) {
    __nv_bfloat162 t;
    t.x = __float2bfloat16(a); t.y = __float2bfloat16(b);
    return *(uint32_t*)&t;
}
__device__ __forceinline__ uint32_t pack_lo(float a, float b) {
    __nv_bfloat16 ha = __float2bfloat16(a), hb = __float2bfloat16(b);
    __nv_bfloat162 t;
    t.x = __float2bfloat16(a - __bfloat162float(ha));
    t.y = __float2bfloat16(b - __bfloat162float(hb));
    return *(uint32_t*)&t;
}

__device__ __forceinline__ float gelu_tanh(float x) {
    float x3 = x * x * x;
    return 0.5f * x * (1.0f + tanhf(0.7978845608f * (x + 0.044715f * x3)));
}

// ------------------------------ device buffers -----------------------------
__device__ float g_big [25165824];  // 8192*3072 qkv fp32
__device__ float g_q   [ 8388608];
__device__ float g_kc  [ 2097152];
__device__ float g_vc  [ 2097152];
__device__ float g_x1  [ 8388608];
__device__ float g_x2  [ 8388608];
__device__ __nv_bfloat16 g_lnh[ 8388608], g_lnl[ 8388608];
__device__ __nv_bfloat16 g_ath[ 8388608], g_atl[ 8388608];
__device__ __nv_bfloat16 g_fch[33554432], g_fcl[33554432];
__device__ __nv_bfloat16 g_imh[ 2097152], g_iml[ 2097152];
__device__ __nv_bfloat16 w_attn_h[3145728], w_attn_l[3145728];
__device__ __nv_bfloat16 w_apr_h [1048576], w_apr_l [1048576];
__device__ __nv_bfloat16 w_q_h   [1048576], w_q_l   [1048576];
__device__ __nv_bfloat16 w_k_h   [1048576], w_k_l   [1048576];
__device__ __nv_bfloat16 w_v_h   [1048576], w_v_l   [1048576];
__device__ __nv_bfloat16 w_cpr_h [1048576], w_cpr_l [1048576];
__device__ __nv_bfloat16 w_fc_h  [4194304], w_fc_l  [4194304];
__device__ __nv_bfloat16 w_mpr_h [4194304], w_mpr_l [4194304];

// ------------------------- weight transpose + split ------------------------
__global__ __launch_bounds__(256) void wtrans(const float* __restrict__ W,
                                              __nv_bfloat16* __restrict__ Th,
                                              __nv_bfloat16* __restrict__ Tl,
                                              int K, int N) {
    __shared__ float t[32][33];
    int tx = threadIdx.x, ty = threadIdx.y;
    int n0 = blockIdx.x * 32, k0 = blockIdx.y * 32;
    #pragma unroll
    for (int i = 0; i < 32; i += 8)
        t[ty + i][tx] = W[(size_t)(k0 + ty + i) * N + n0 + tx];
    __syncthreads();
    #pragma unroll
    for (int i = 0; i < 32; i += 8) {
        float v = t[tx][ty + i];
        __nv_bfloat16 h, l;
        split_bf16(v, h, l);
        size_t o = (size_t)(n0 + ty + i) * K + k0 + tx;
        Th[o] = h; Tl[o] = l;
    }
}

__global__ __launch_bounds__(256) void fsplit(const float* __restrict__ x,
                                              __nv_bfloat16* __restrict__ oh,
                                              __nv_bfloat16* __restrict__ ol) {
    size_t i = ((size_t)blockIdx.x * 256 + threadIdx.x) * 4;
    float4 v = *(const float4*)(x + i);
    *(uint32_t*)(oh + i)     = pack_hi(v.x, v.y);
    *(uint32_t*)(oh + i + 2) = pack_hi(v.z, v.w);
    *(uint32_t*)(ol + i)     = pack_lo(v.x, v.y);
    *(uint32_t*)(ol + i + 2) = pack_lo(v.z, v.w);
}

// ------------------------------ LayerNorm ----------------------------------
__global__ __launch_bounds__(256) void ln_kernel(const float* __restrict__ x,
                                                 const float* __restrict__ gam,
                                                 const float* __restrict__ bet,
                                                 __nv_bfloat16* __restrict__ oh,
                                                 __nv_bfloat16* __restrict__ ol) {
    __shared__ float sred[8];
    int row = blockIdx.x;
    int t = threadIdx.x;
    const float* xr = x + (size_t)row * 1024;
    float4 v = *(const float4*)(xr + t * 4);
    float s = v.x + v.y + v.z + v.w;
    #pragma unroll
    for (int o = 16; o > 0; o >>= 1) s += __shfl_xor_sync(0xffffffffu, s, o);
    if ((t & 31) == 0) sred[t >> 5] = s;
    __syncthreads();
    float mu = 0.f;
    #pragma unroll
    for (int i = 0; i < 8; i++) mu += sred[i];
    mu *= (1.0f / 1024.0f);
    __syncthreads();
    float dx = v.x - mu, dy = v.y - mu, dz = v.z - mu, dw = v.w - mu;
    float ss = dx * dx + dy * dy + dz * dz + dw * dw;
    #pragma unroll
    for (int o = 16; o > 0; o >>= 1) ss += __shfl_xor_sync(0xffffffffu, ss, o);
    if ((t & 31) == 0) sred[t >> 5] = ss;
    __syncthreads();
    float var = 0.f;
    #pragma unroll
    for (int i = 0; i < 8; i++) var += sred[i];
    var *= (1.0f / 1024.0f);
    float rstd = rsqrtf(var + 1e-5f);
    float4 gv = *(const float4*)(gam + t * 4);
    float4 bv = *(const float4*)(bet + t * 4);
    float r0 = dx * rstd * gv.x + bv.x;
    float r1 = dy * rstd * gv.y + bv.y;
    float r2 = dz * rstd * gv.z + bv.z;
    float r3 = dw * rstd * gv.w + bv.w;
    size_t o = (size_t)row * 1024 + t * 4;
    *(uint32_t*)(oh + o)     = pack_hi(r0, r1);
    *(uint32_t*)(oh + o + 2) = pack_hi(r2, r3);
    *(uint32_t*)(ol + o)     = pack_lo(r0, r1);
    *(uint32_t*)(ol + o + 2) = pack_lo(r2, r3);
}

// ---------------------------- HMMA GEMM ------------------------------------
template<int MODE>
__global__ __launch_bounds__(512) void hmma_gemm(
    const __nv_bfloat16* __restrict__ Ah, const __nv_bfloat16* __restrict__ Al,
    const __nv_bfloat16* __restrict__ Bh, const __nv_bfloat16* __restrict__ Bl,
    const float* __restrict__ bias, const float* __restrict__ res,
    float* __restrict__ outf,
    __nv_bfloat16* __restrict__ outh, __nv_bfloat16* __restrict__ outl,
    int M, int N, int K) {
    extern __shared__ __align__(128) uint8_t smem[];
    const uint32_t STG = 40960;
    const uint32_t OA_H = 0, OA_L = 10240, OB_H = 20480, OB_L = 30720;
    uint32_t sb = smem_u32(smem);
    int tid = threadIdx.x, wid = tid >> 5, lane = tid & 31;
    int row0 = blockIdx.y * 128, col0 = blockIdx.x * 128;
    int wm = wid >> 2, wn = wid & 3;

    int lrow = tid >> 2, lseg = tid & 3;
    size_t ga = (size_t)(row0 + lrow) * K + lseg * 8;
    size_t gb = (size_t)(col0 + lrow) * K + lseg * 8;
    uint32_t so = lrow * 80 + lseg * 16;

    float c[2][4][4];
    #pragma unroll
    for (int i = 0; i < 2; i++)
        #pragma unroll
        for (int j = 0; j < 4; j++)
            #pragma unroll
            for (int q = 0; q < 4; q++) c[i][j][q] = 0.f;

    const int nk = K >> 5;
    {
        uint32_t d = sb + so;
        CP16(d + OA_H, Ah + ga); CP16(d + OA_L, Al + ga);
        CP16(d + OB_H, Bh + gb); CP16(d + OB_L, Bl + gb);
        CP_COMMIT();
    }
    for (int ch = 0; ch < nk; ch++) {
        if (ch + 1 < nk) {
            uint32_t d = sb + ((ch + 1) & 1) * STG + so;
            int ko = (ch + 1) << 5;
            CP16(d + OA_H, Ah + ga + ko); CP16(d + OA_L, Al + ga + ko);
            CP16(d + OB_H, Bh + gb + ko); CP16(d + OB_L, Bl + gb + ko);
            CP_COMMIT();
            CP_WAIT1();
        } else {
            CP_WAIT0();
        }
        __syncthreads();
        uint32_t base = sb + (ch & 1) * STG;

        #pragma unroll
        for (int s = 0; s < 2; s++) {
            uint32_t ah[2][4], al[2][4], bh[2][4], bl[2][4];
            #pragma unroll
            for (int mb = 0; mb < 2; mb++) {
                uint32_t ra = base + OA_H +
                    (uint32_t)(wm * 32 + mb * 16 + (lane & 15)) * 80 + s * 32 + (lane >> 4) * 16;
                LDSM4(ah[mb][0], ah[mb][1], ah[mb][2], ah[mb][3], ra);
                uint32_t rl = ra + (OA_L - OA_H);
                LDSM4(al[mb][0], al[mb][1], al[mb][2], al[mb][3], rl);
            }
            {
                int grp = lane >> 3, idx = lane & 7;
                #pragma unroll
                for (int nb = 0; nb < 2; nb++) {
                    uint32_t rb = base + OB_H +
                        (uint32_t)(wn * 32 + nb * 16 + ((grp >> 1) << 3) + idx) * 80 +
                        s * 32 + (grp & 1) * 16;
                    LDSM4(bh[nb][0], bh[nb][1], bh[nb][2], bh[nb][3], rb);
                    uint32_t rbl = rb + (OB_L - OB_H);
                    LDSM4(bl[nb][0], bl[nb][1], bl[nb][2], bl[nb][3], rbl);
                }
            }
            #pragma unroll
            for (int mb = 0; mb < 2; mb++) {
                #pragma unroll
                for (int j = 0; j < 4; j++) {
                    int nb = j >> 1, k2 = (j & 1) * 2;
                    uint32_t b0h = bh[nb][k2], b1h = bh[nb][k2 + 1];
                    uint32_t b0l = bl[nb][k2], b1l = bl[nb][k2 + 1];
                    MMA_BF16(c[mb][j], ah[mb], b0h, b1h);
                    MMA_BF16(c[mb][j], ah[mb], b0l, b1l);
                    MMA_BF16(c[mb][j], al[mb], b0h, b1h);
                }
            }
        }
        __syncthreads();
    }

    #pragma unroll
    for (int mb = 0; mb < 2; mb++) {
        #pragma unroll
        for (int j = 0; j < 4; j++) {
            int col = col0 + wn * 32 + j * 8 + 2 * (lane & 3);
            float2 bv = *(const float2*)(bias + col);
            #pragma unroll
            for (int half = 0; half < 2; half++) {
                int r = row0 + wm * 32 + mb * 16 + (lane >> 2) + half * 8;
                float v0 = c[mb][j][half * 2 + 0] + bv.x;
                float v1 = c[mb][j][half * 2 + 1] + bv.y;
                if (MODE == 1) {
                    float2 rv = *(const float2*)(res + (size_t)r * N + col);
                    v0 += rv.x; v1 += rv.y;
                }
                if (MODE == 2) {
                    v0 = gelu_tanh(v0); v1 = gelu_tanh(v1);
                    size_t o = (size_t)r * N + col;
                    *(uint32_t*)(outh + o) = pack_hi(v0, v1);
                    *(uint32_t*)(outl + o) = pack_lo(v0, v1);
                } else {
                    *(float2*)(outf + (size_t)r * N + col) = make_float2(v0, v1);
                }
            }
        }
    }
}

// ------------------------- Flash attention (HMMA) --------------------------
// 128-query x 64-key tiles, D=64. 8 warps, each owns m16 x n64 of S.
// Q/K/V split bf16 hi/lo, 3 MMA products per logical GEMM. P stays in
// registers (S C-frag layout == PV A-frag layout). V staged transposed.
template<bool CAUSAL>
__global__ __launch_bounds__(256) void flash_mma(const float* __restrict__ Qb,
                                                 const float* __restrict__ Kb,
                                                 const float* __restrict__ Vb,
                                                 __nv_bfloat16* __restrict__ Oh,
                                                 __nv_bfloat16* __restrict__ Ol,
                                                 int Tq, int Tk,
                                                 int qrs, int krs, int vrs,
                                                 float scale) {
    // smem: phase 1 Q[128][72] hi/lo (2*18432B); phase 2 K hi/lo + Vt hi/lo (4*9216B)
    __shared__ __align__(16) uint8_t smem[36864];
    uint32_t sb = smem_u32(smem);
    const uint32_t QH = 0, QL = 18432;
    const uint32_t KH = 0, KL = 9216, VTH = 18432, VTL = 27648;

    int tid = threadIdx.x, wid = tid >> 5, lane = tid & 31;
    int g = lane >> 2, qd = lane & 3;
    int bh = blockIdx.y, b = bh >> 4, h = bh & 15;
    int q0 = blockIdx.x * 128;
    const float* Qbase = Qb + (size_t)b * Tq * qrs + h * 64;
    const float* Kbase = Kb + (size_t)b * Tk * krs + h * 64;
    const float* Vbase = Vb + (size_t)b * Tk * vrs + h * 64;

    // ---- stage Q (scaled, split) then load persistent A frags ----
    #pragma unroll
    for (int it = 0; it < 8; it++) {
        int lin = tid + it * 256;           // 128 rows x 16 float4 segs
        int r = lin >> 4, d4 = (lin & 15) * 4;
        float4 v = *(const float4*)(Qbase + (size_t)(q0 + r) * qrs + d4);
        v.x *= scale; v.y *= scale; v.z *= scale; v.w *= scale;
        uint32_t off = (uint32_t)(r * 72 + d4) * 2;
        *(uint32_t*)(smem + QH + off)     = pack_hi(v.x, v.y);
        *(uint32_t*)(smem + QH + off + 4) = pack_hi(v.z, v.w);
        *(uint32_t*)(smem + QL + off)     = pack_lo(v.x, v.y);
        *(uint32_t*)(smem + QL + off + 4) = pack_lo(v.z, v.w);
    }
    __syncthreads();
    uint32_t qh[4][4], ql[4][4];
    #pragma unroll
    for (int s = 0; s < 4; s++) {
        uint32_t ra = sb + QH + (uint32_t)(wid * 16 + (lane & 15)) * 144 + s * 32 + (lane >> 4) * 16;
        LDSM4(qh[s][0], qh[s][1], qh[s][2], qh[s][3], ra);
        uint32_t rl = ra + (QL - QH);
        LDSM4(ql[s][0], ql[s][1], ql[s][2], ql[s][3], rl);
    }
    __syncthreads();    // Q consumed; smem reused for K/V

    float o[8][4];
    #pragma unroll
    for (int j = 0; j < 8; j++)
        #pragma unroll
        for (int q = 0; q < 4; q++) o[j][q] = 0.f;
    float mrow[2] = {-1e30f, -1e30f};
    float lrow[2] = {0.f, 0.f};

    int nt = CAUSAL ? (2 * blockIdx.x + 2) : (Tk >> 6);
    for (int kt = 0; kt < nt; kt++) {
        int k0 = kt * 64;
        // ---- load K (row-major) and V (transposed) split ----
        #pragma unroll
        for (int it = 0; it < 4; it++) {
            int lin = tid + it * 256;       // 64 rows x 16 segs
            int s = lin >> 4, d4 = (lin & 15) * 4;
            float4 kv = *(const float4*)(Kbase + (size_t)(k0 + s) * krs + d4);
            uint32_t off = (uint32_t)(s * 72 + d4) * 2;
            *(uint32_t*)(smem + KH + off)     = pack_hi(kv.x, kv.y);
            *(uint32_t*)(smem + KH + off + 4) = pack_hi(kv.z, kv.w);
            *(uint32_t*)(smem + KL + off)     = pack_lo(kv.x, kv.y);
            *(uint32_t*)(smem + KL + off + 4) = pack_lo(kv.z, kv.w);
            float4 vv = *(const float4*)(Vbase + (size_t)(k0 + s) * vrs + d4);
            float va[4] = {vv.x, vv.y, vv.z, vv.w};
            #pragma unroll
            for (int i = 0; i < 4; i++) {
                __nv_bfloat16 hh, ll;
                split_bf16(va[i], hh, ll);
                uint32_t to = (uint32_t)((d4 + i) * 72 + s) * 2;
                *(__nv_bfloat16*)(smem + VTH + to) = hh;
                *(__nv_bfloat16*)(smem + VTL + to) = ll;
            }
        }
        __syncthreads();

        // ---- S = Q K^T (per-warp 16x64) ----
        float sc[8][4];
        #pragma unroll
        for (int j = 0; j < 8; j++)
            #pragma unroll
            for (int q = 0; q < 4; q++) sc[j][q] = 0.f;
        int grp = lane >> 3, idx = lane & 7;
        #pragma unroll
        for (int s = 0; s < 4; s++) {
            #pragma unroll
            for (int nb4 = 0; nb4 < 4; nb4++) {
                uint32_t kh[4], kl[4];
                uint32_t rb = sb + KH +
                    (uint32_t)(nb4 * 16 + ((grp >> 1) << 3) + idx) * 144 + s * 32 + (grp & 1) * 16;
                LDSM4(kh[0], kh[1], kh[2], kh[3], rb);
                uint32_t rbl = rb + (KL - KH);
                LDSM4(kl[0], kl[1], kl[2], kl[3], rbl);
                #pragma unroll
                for (int jj = 0; jj < 2; jj++) {
                    MMA_BF16(sc[nb4 * 2 + jj], qh[s], kh[jj * 2], kh[jj * 2 + 1]);
                    MMA_BF16(sc[nb4 * 2 + jj], qh[s], kl[jj * 2], kl[jj * 2 + 1]);
                    MMA_BF16(sc[nb4 * 2 + jj], ql[s], kh[jj * 2], kh[jj * 2 + 1]);
                }
            }
        }

        // ---- causal mask ----
        if (CAUSAL && (k0 + 63 > q0 + wid * 16)) {
            #pragma unroll
            for (int jb = 0; jb < 8; jb++) {
                #pragma unroll
                for (int q = 0; q < 4; q++) {
                    int col = k0 + jb * 8 + 2 * qd + (q & 1);
                    int row = q0 + wid * 16 + g + ((q >> 1) << 3);
                    if (col > row) sc[jb][q] = -1e30f;
                }
            }
        }

        // ---- online softmax (rows g and g+8; 4 lanes per row) ----
        #pragma unroll
        for (int rh = 0; rh < 2; rh++) {
            float mx = -1e30f;
            #pragma unroll
            for (int jb = 0; jb < 8; jb++)
                mx = fmaxf(mx, fmaxf(sc[jb][rh * 2], sc[jb][rh * 2 + 1]));
            mx = fmaxf(mx, __shfl_xor_sync(0xffffffffu, mx, 1));
            mx = fmaxf(mx, __shfl_xor_sync(0xffffffffu, mx, 2));
            float mnew = fmaxf(mrow[rh], mx);
            float alpha = __expf(mrow[rh] - mnew);
            float ps = 0.f;
            #pragma unroll
            for (int jb = 0; jb < 8; jb++) {
                float p0 = __expf(sc[jb][rh * 2]     - mnew);
                float p1 = __expf(sc[jb][rh * 2 + 1] - mnew);
                sc[jb][rh * 2] = p0; sc[jb][rh * 2 + 1] = p1;
                ps += p0 + p1;
            }
            ps += __shfl_xor_sync(0xffffffffu, ps, 1);
            ps += __shfl_xor_sync(0xffffffffu, ps, 2);
            lrow[rh] = lrow[rh] * alpha + ps;
            mrow[rh] = mnew;
            #pragma unroll
            for (int jb = 0; jb < 8; jb++) {
                o[jb][rh * 2] *= alpha; o[jb][rh * 2 + 1] *= alpha;
            }
        }

        // ---- O += P V : P frags from registers, Vt B frags from smem ----
        #pragma unroll
        for (int w = 0; w < 4; w++) {
            uint32_t pah[4], pal[4];
            pah[0] = pack_hi(sc[2 * w][0], sc[2 * w][1]);
            pah[1] = pack_hi(sc[2 * w][2], sc[2 * w][3]);
            pah[2] = pack_hi(sc[2 * w + 1][0], sc[2 * w + 1][1]);
            pah[3] = pack_hi(sc[2 * w + 1][2], sc[2 * w + 1][3]);
            pal[0] = pack_lo(sc[2 * w][0], sc[2 * w][1]);
            pal[1] = pack_lo(sc[2 * w][2], sc[2 * w][3]);
            pal[2] = pack_lo(sc[2 * w + 1][0], sc[2 * w + 1][1]);
            pal[3] = pack_lo(sc[2 * w + 1][2], sc[2 * w + 1][3]);
            #pragma unroll
            for (int db4 = 0; db4 < 4; db4++) {
                uint32_t vh[4], vl[4];
                uint32_t rb = sb + VTH +
                    (uint32_t)(db4 * 16 + ((grp >> 1) << 3) + idx) * 144 + w * 32 + (grp & 1) * 16;
                LDSM4(vh[0], vh[1], vh[2], vh[3], rb);
                uint32_t rbl = rb + (VTL - VTH);
                LDSM4(vl[0], vl[1], vl[2], vl[3], rbl);
                #pragma unroll
                for (int jj = 0; jj < 2; jj++) {
                    MMA_BF16(o[db4 * 2 + jj], pah, vh[jj * 2], vh[jj * 2 + 1]);
                    MMA_BF16(o[db4 * 2 + jj], pah, vl[jj * 2], vl[jj * 2 + 1]);
                    MMA_BF16(o[db4 * 2 + jj], pal, vh[jj * 2], vh[jj * 2 + 1]);
                }
            }
        }
        __syncthreads();    // all reads of K/Vt done before next tile's stores
    }

    // ---- epilogue: O/l -> bf16 hi/lo ----
    #pragma unroll
    for (int rh = 0; rh < 2; rh++) {
        float inv = 1.0f / lrow[rh];
        int r = q0 + wid * 16 + g + rh * 8;
        size_t rowb = (size_t)(b * Tq + r) * 1024 + h * 64;
        #pragma unroll
        for (int jb = 0; jb < 8; jb++) {
            int d = jb * 8 + 2 * qd;
            float v0 = o[jb][rh * 2] * inv, v1 = o[jb][rh * 2 + 1] * inv;
            *(uint32_t*)(Oh + rowb + d) = pack_hi(v0, v1);
            *(uint32_t*)(Ol + rowb + d) = pack_lo(v0, v1);
        }
    }
}

// ------------------------------ Launch -------------------------------------
extern "C" void kernel_launch(void* const* d_in, const int* in_sizes, int n_in,
                              void* d_out, int out_size) {
    (void)in_sizes; (void)n_in; (void)out_size;
    const float* x       = (const float*)d_in[0];
    const float* ximg    = (const float*)d_in[1];
    const float* ln1g    = (const float*)d_in[2];
    const float* ln1b    = (const float*)d_in[3];
    const float* ln2g    = (const float*)d_in[4];
    const float* ln2b    = (const float*)d_in[5];
    const float* W_attn  = (const float*)d_in[6];
    const float* b_attn  = (const float*)d_in[7];
    const float* W_aproj = (const float*)d_in[8];
    const float* b_aproj = (const float*)d_in[9];
    const float* Wq      = (const float*)d_in[10];
    const float* bq      = (const float*)d_in[11];
    const float* Wk      = (const float*)d_in[12];
    const float* bk      = (const float*)d_in[13];
    const float* Wv      = (const float*)d_in[14];
    const float* bv      = (const float*)d_in[15];
    const float* Wcproj  = (const float*)d_in[16];
    const float* bcproj  = (const float*)d_in[17];
    const float* W_fc    = (const float*)d_in[18];
    const float* b_fc    = (const float*)d_in[19];
    const float* W_mproj = (const float*)d_in[20];
    const float* b_mproj = (const float*)d_in[21];
    float* out = (float*)d_out;

    float *p_big, *p_q, *p_kc, *p_vc, *p_x1, *p_x2;
    __nv_bfloat16 *p_lnh, *p_lnl, *p_ath, *p_atl, *p_fch, *p_fcl, *p_imh, *p_iml;
    __nv_bfloat16 *pw_attn_h, *pw_attn_l, *pw_apr_h, *pw_apr_l, *pw_q_h, *pw_q_l;
    __nv_bfloat16 *pw_k_h, *pw_k_l, *pw_v_h, *pw_v_l, *pw_cpr_h, *pw_cpr_l;
    __nv_bfloat16 *pw_fc_h, *pw_fc_l, *pw_mpr_h, *pw_mpr_l;
    cudaGetSymbolAddress((void**)&p_big, g_big);
    cudaGetSymbolAddress((void**)&p_q,   g_q);
    cudaGetSymbolAddress((void**)&p_kc,  g_kc);
    cudaGetSymbolAddress((void**)&p_vc,  g_vc);
    cudaGetSymbolAddress((void**)&p_x1,  g_x1);
    cudaGetSymbolAddress((void**)&p_x2,  g_x2);
    cudaGetSymbolAddress((void**)&p_lnh, g_lnh);
    cudaGetSymbolAddress((void**)&p_lnl, g_lnl);
    cudaGetSymbolAddress((void**)&p_ath, g_ath);
    cudaGetSymbolAddress((void**)&p_atl, g_atl);
    cudaGetSymbolAddress((void**)&p_fch, g_fch);
    cudaGetSymbolAddress((void**)&p_fcl, g_fcl);
    cudaGetSymbolAddress((void**)&p_imh, g_imh);
    cudaGetSymbolAddress((void**)&p_iml, g_iml);
    cudaGetSymbolAddress((void**)&pw_attn_h, w_attn_h);
    cudaGetSymbolAddress((void**)&pw_attn_l, w_attn_l);
    cudaGetSymbolAddress((void**)&pw_apr_h, w_apr_h);
    cudaGetSymbolAddress((void**)&pw_apr_l, w_apr_l);
    cudaGetSymbolAddress((void**)&pw_q_h, w_q_h);
    cudaGetSymbolAddress((void**)&pw_q_l, w_q_l);
    cudaGetSymbolAddress((void**)&pw_k_h, w_k_h);
    cudaGetSymbolAddress((void**)&pw_k_l, w_k_l);
    cudaGetSymbolAddress((void**)&pw_v_h, w_v_h);
    cudaGetSymbolAddress((void**)&pw_v_l, w_v_l);
    cudaGetSymbolAddress((void**)&pw_cpr_h, w_cpr_h);
    cudaGetSymbolAddress((void**)&pw_cpr_l, w_cpr_l);
    cudaGetSymbolAddress((void**)&pw_fc_h, w_fc_h);
    cudaGetSymbolAddress((void**)&pw_fc_l, w_fc_l);
    cudaGetSymbolAddress((void**)&pw_mpr_h, w_mpr_h);
    cudaGetSymbolAddress((void**)&pw_mpr_l, w_mpr_l);

    const int SMEM_GEMM = 81920;
    cudaFuncSetAttribute(hmma_gemm<0>, cudaFuncAttributeMaxDynamicSharedMemorySize, SMEM_GEMM);
    cudaFuncSetAttribute(hmma_gemm<1>, cudaFuncAttributeMaxDynamicSharedMemorySize, SMEM_GEMM);
    cudaFuncSetAttribute(hmma_gemm<2>, cudaFuncAttributeMaxDynamicSharedMemorySize, SMEM_GEMM);

    const float scale = 0.125f;  // 1/sqrt(64)
    dim3 tb(32, 8);

    // Launch order arranged so launch index 5 (ncu -s 5 -c 1) = qkv GEMM.
    ln_kernel<<<8192, 256>>>(x, ln1g, ln1b, p_lnh, p_lnl);                       // 0
    wtrans<<<dim3(96, 32), tb>>>(W_attn, pw_attn_h, pw_attn_l, 1024, 3072);      // 1
    wtrans<<<dim3(32, 32), tb>>>(W_aproj, pw_apr_h, pw_apr_l, 1024, 1024);       // 2
    wtrans<<<dim3(32, 32), tb>>>(Wq, pw_q_h, pw_q_l, 1024, 1024);                // 3
    wtrans<<<dim3(32, 32), tb>>>(Wk, pw_k_h, pw_k_l, 1024, 1024);                // 4
    hmma_gemm<0><<<dim3(24, 64), 512, SMEM_GEMM>>>(p_lnh, p_lnl, pw_attn_h, pw_attn_l,
                                                   b_attn, nullptr, p_big, nullptr, nullptr,
                                                   8192, 3072, 1024);            // 5 <- ncu
    wtrans<<<dim3(32, 32), tb>>>(Wv, pw_v_h, pw_v_l, 1024, 1024);                // 6
    wtrans<<<dim3(32, 32), tb>>>(Wcproj, pw_cpr_h, pw_cpr_l, 1024, 1024);        // 7
    wtrans<<<dim3(128, 32), tb>>>(W_fc, pw_fc_h, pw_fc_l, 1024, 4096);           // 8
    wtrans<<<dim3(32, 128), tb>>>(W_mproj, pw_mpr_h, pw_mpr_l, 4096, 1024);      // 9
    fsplit<<<2048, 256>>>(ximg, p_imh, p_iml);                                   // 10

    // causal self-attention -> bf16 hi/lo
    flash_mma<true><<<dim3(8, 128), 256>>>(p_big, p_big + 1024, p_big + 2048,
                                           p_ath, p_atl, 1024, 1024,
                                           3072, 3072, 3072, scale);
    // x1 = sa @ W_aproj + b + x
    hmma_gemm<1><<<dim3(8, 64), 512, SMEM_GEMM>>>(p_ath, p_atl, pw_apr_h, pw_apr_l,
                                                  b_aproj, x, p_x1, nullptr, nullptr,
                                                  8192, 1024, 1024);
    ln_kernel<<<8192, 256>>>(p_x1, ln1g, ln1b, p_lnh, p_lnl);
    hmma_gemm<0><<<dim3(8, 64), 512, SMEM_GEMM>>>(p_lnh, p_lnl, pw_q_h, pw_q_l,
                                                  bq, nullptr, p_q, nullptr, nullptr,
                                                  8192, 1024, 1024);
    hmma_gemm<0><<<dim3(8, 16), 512, SMEM_GEMM>>>(p_imh, p_iml, pw_k_h, pw_k_l,
                                                  bk, nullptr, p_kc, nullptr, nullptr,
                                                  2048, 1024, 1024);
    hmma_gemm<0><<<dim3(8, 16), 512, SMEM_GEMM>>>(p_imh, p_iml, pw_v_h, pw_v_l,
                                                  bv, nullptr, p_vc, nullptr, nullptr,
                                                  2048, 1024, 1024);
    // cross attention -> bf16 hi/lo
    flash_mma<false><<<dim3(8, 128), 256>>>(p_q, p_kc, p_vc, p_ath, p_atl,
                                            1024, 256, 1024, 1024, 1024, scale);
    hmma_gemm<1><<<dim3(8, 64), 512, SMEM_GEMM>>>(p_ath, p_atl, pw_cpr_h, pw_cpr_l,
                                                  bcproj, p_x1, p_x2, nullptr, nullptr,
                                                  8192, 1024, 1024);
    ln_kernel<<<8192, 256>>>(p_x2, ln2g, ln2b, p_lnh, p_lnl);
    hmma_gemm<2><<<dim3(32, 64), 512, SMEM_GEMM>>>(p_lnh, p_lnl, pw_fc_h, pw_fc_l,
                                                   b_fc, nullptr, nullptr, p_fch, p_fcl,
                                                   8192, 4096, 1024);
    hmma_gemm<1><<<dim3(8, 64), 512, SMEM_GEMM>>>(p_fch, p_fcl, pw_mpr_h, pw_mpr_l,
                                                  b_mproj, p_x2, out, nullptr, nullptr,
                                                  8192, 1024, 4096);
}